// round 4
// baseline (speedup 1.0000x reference)
#include <cuda_runtime.h>
#include <math.h>

// Problem constants
#define K_DIM 13
#define N_DIM 4096
#define IK    416                 // I*K = 32*13
#define WSIZE 13312               // O*IK = 32*416 floats = 53 KB
#define NPG   2                   // n's per iteration group
#define NGROUPS (N_DIM / NPG)     // 2048
#define THREADS 1024              // 32 warps, warp == o
#define BLOCKS  304               // 152 SMs * 2 resident

__global__ void __launch_bounds__(THREADS, 2) plaq_kernel(
    const float* __restrict__ x,       // (I, N)
    const float* __restrict__ W,       // (O, I, K)
    const float* __restrict__ b,       // (O,)
    const float* __restrict__ mask,    // (N, O, I, K)
    const int*   __restrict__ shifts,  // (N, K)
    float*       __restrict__ out)     // (O, N)
{
    __shared__ __align__(16) float Wsh[WSIZE];
    __shared__ __align__(16) float gsh[2][NPG][IK];

    const int tid  = threadIdx.x;
    const int warp = tid >> 5;   // warp == o
    const int lane = tid & 31;

    // Load W once per block
    for (int e = tid; e < WSIZE; e += THREADS)
        Wsh[e] = W[e];

    // Gather coordinates: threads 0..831 each own one (nl, e) element
    const int  nl   = tid / IK;            // 0 or 1
    const int  ge   = tid - nl * IK;
    const int  gi   = ge / K_DIM;
    const int  gk   = ge - gi * K_DIM;
    const bool gact = (tid < NPG * IK);

    // Prime group 0's gather buffer
    int g = blockIdx.x;
    if (gact) {
        const int n = g * NPG + nl;
        gsh[0][nl][ge] = x[gi * N_DIM + shifts[n * K_DIM + gk]];
    }
    __syncthreads();

    const float bias = b[warp];
    const float e_const = 2.718281828459045f;
    const float scale = (2.0f + 2.0f * e_const) / (e_const - 1.0f);

    const float4* __restrict__ w4 = (const float4*)(Wsh + warp * IK);

    int p = 0;
    for (; g < NGROUPS; g += BLOCKS) {
        // ---- Prefetch next group's gather into a register (hides shifts->x chain)
        const int  gn = g + BLOCKS;
        const bool pf = gact && (gn < NGROUPS);
        float gv = 0.0f;
        if (pf) {
            const int n = gn * NPG + nl;
            gv = x[gi * N_DIM + shifts[n * K_DIM + gk]];
        }

        // ---- Dot for the 2 n's of this group (float4 streams)
        const int n0 = g * NPG;
        const float4* __restrict__ m0 =
            (const float4*)(mask + ((size_t)n0 * 32 + warp) * IK);
        const float4* __restrict__ m1 =
            (const float4*)(mask + ((size_t)(n0 + 1) * 32 + warp) * IK);
        const float4* __restrict__ g0 = (const float4*)gsh[p][0];
        const float4* __restrict__ g1 = (const float4*)gsh[p][1];

        float s0 = 0.0f, s1 = 0.0f;
        #pragma unroll
        for (int j = 0; j < 3; ++j) {
            const int c = j * 32 + lane;
            const float4 w  = w4[c];
            const float4 a0 = m0[c];
            const float4 ga = g0[c];
            s0 += a0.x*w.x*ga.x + a0.y*w.y*ga.y + a0.z*w.z*ga.z + a0.w*w.w*ga.w;
            const float4 a1 = m1[c];
            const float4 gb = g1[c];
            s1 += a1.x*w.x*gb.x + a1.y*w.y*gb.y + a1.z*w.z*gb.z + a1.w*w.w*gb.w;
        }
        if (lane < 8) {   // tail chunks 96..103
            const int c = 96 + lane;
            const float4 w  = w4[c];
            const float4 a0 = m0[c];
            const float4 ga = g0[c];
            s0 += a0.x*w.x*ga.x + a0.y*w.y*ga.y + a0.z*w.z*ga.z + a0.w*w.w*ga.w;
            const float4 a1 = m1[c];
            const float4 gb = g1[c];
            s1 += a1.x*w.x*gb.x + a1.y*w.y*gb.y + a1.z*w.z*gb.z + a1.w*w.w*gb.w;
        }

        // ---- Warp reductions (both n's interleaved)
        #pragma unroll
        for (int off = 16; off > 0; off >>= 1) {
            s0 += __shfl_xor_sync(0xffffffffu, s0, off);
            s1 += __shfl_xor_sync(0xffffffffu, s1, off);
        }

        if (lane == 0) {
            const float y0 = s0 + bias;
            const float y1 = s1 + bias;
            out[warp * N_DIM + n0]     = (1.0f / (1.0f + __expf(-y0)) - 0.5f) * scale;
            out[warp * N_DIM + n0 + 1] = (1.0f / (1.0f + __expf(-y1)) - 0.5f) * scale;
        }

        // ---- Commit prefetched gather, flip buffers
        if (pf) gsh[p ^ 1][nl][ge] = gv;
        __syncthreads();
        p ^= 1;
    }
}

extern "C" void kernel_launch(void* const* d_in, const int* in_sizes, int n_in,
                              void* d_out, int out_size) {
    const float* x      = (const float*)d_in[0];
    const float* Wconv  = (const float*)d_in[1];
    const float* bconv  = (const float*)d_in[2];
    const float* mask   = (const float*)d_in[3];
    const int*   shifts = (const int*)d_in[4];
    float* out          = (float*)d_out;

    plaq_kernel<<<BLOCKS, THREADS>>>(x, Wconv, bconv, mask, shifts, out);
}

// round 5
// speedup vs baseline: 1.1643x; 1.1643x over previous
#include <cuda_runtime.h>
#include <cstdint>
#include <math.h>

// Problem constants
#define K_DIM 13
#define N_DIM 4096
#define IK    416                          // I*K
#define ROW_FLOATS 13312                   // O*IK = one n's mask slab
#define ROW_BYTES  53248
#define DEPTH   4
#define THREADS 1024
#define GRID    152

// Dynamic smem layout
#define MASK_OFF 0
#define G_OFF    (DEPTH * ROW_BYTES)                 // 212992
#define BAR_OFF  (G_OFF + DEPTH * IK * 4)            // 219648
#define SMEM_TOTAL (BAR_OFF + DEPTH * 8)             // 219680

// ---- PTX helpers -----------------------------------------------------------
__device__ __forceinline__ uint32_t smem_u32(const void* p) {
    return (uint32_t)__cvta_generic_to_shared(p);
}
__device__ __forceinline__ void mbar_init(uint32_t a, uint32_t cnt) {
    asm volatile("mbarrier.init.shared.b64 [%0], %1;" :: "r"(a), "r"(cnt) : "memory");
}
__device__ __forceinline__ void mbar_arrive(uint32_t a) {
    asm volatile("mbarrier.arrive.shared.b64 _, [%0];" :: "r"(a) : "memory");
}
__device__ __forceinline__ void mbar_expect_tx(uint32_t a, uint32_t bytes) {
    asm volatile("mbarrier.arrive.expect_tx.shared.b64 _, [%0], %1;"
                 :: "r"(a), "r"(bytes) : "memory");
}
__device__ __forceinline__ void mbar_wait(uint32_t a, uint32_t parity) {
    uint32_t done;
    asm volatile(
        "{\n\t.reg .pred p;\n\t"
        "mbarrier.try_wait.parity.acquire.cta.shared::cta.b64 p, [%1], %2;\n\t"
        "selp.b32 %0, 1, 0, p;\n\t}"
        : "=r"(done) : "r"(a), "r"(parity) : "memory");
    if (!done) {
        asm volatile(
            "{\n\t.reg .pred P1;\n\t"
            "WL_%=:\n\t"
            "mbarrier.try_wait.parity.acquire.cta.shared::cta.b64 P1, [%0], %1, 0x989680;\n\t"
            "@P1 bra.uni WD_%=;\n\t"
            "bra.uni WL_%=;\n\t"
            "WD_%=:\n\t}"
            :: "r"(a), "r"(parity) : "memory");
    }
}
__device__ __forceinline__ void bulk_copy_g2s(uint32_t dst, const void* src,
                                              uint32_t bytes, uint32_t mbar) {
    asm volatile(
        "cp.async.bulk.shared::cluster.global.mbarrier::complete_tx::bytes "
        "[%0], [%1], %2, [%3];"
        :: "r"(dst), "l"(src), "r"(bytes), "r"(mbar) : "memory");
}
// -----------------------------------------------------------------------------

extern __shared__ __align__(128) unsigned char smem_raw[];

__global__ void __launch_bounds__(THREADS, 1) plaq_kernel(
    const float* __restrict__ x,       // (I, N)
    const float* __restrict__ W,       // (O, I, K)
    const float* __restrict__ b,       // (O,)
    const float* __restrict__ mask,    // (N, O, I, K)
    const int*   __restrict__ shifts,  // (N, K)
    float*       __restrict__ out)     // (O, N)
{
    float* msh = (float*)(smem_raw + MASK_OFF);   // DEPTH x ROW_FLOATS
    float* gsh = (float*)(smem_raw + G_OFF);      // DEPTH x IK
    const uint32_t smem_base = smem_u32(smem_raw);
    const uint32_t bar_base  = smem_base + BAR_OFF;

    const int tid  = threadIdx.x;
    const int warp = tid >> 5;   // warp == o
    const int lane = tid & 31;

    // Init barriers: 416 gather arrivals + 1 expect_tx arrival per phase
    if (tid == 0) {
        #pragma unroll
        for (int s = 0; s < DEPTH; ++s)
            mbar_init(bar_base + s * 8, IK + 1);
    }
    __syncthreads();

    // Hoist this warp's W row into registers as float4 chunks
    float4 wf[4];
    {
        const float4* W4 = (const float4*)(W + warp * IK);
        #pragma unroll
        for (int j = 0; j < 3; ++j) wf[j] = W4[j * 32 + lane];
        wf[3] = (lane < 8) ? W4[96 + lane] : make_float4(0.f, 0.f, 0.f, 0.f);
    }
    const float bias = b[warp];
    const float e_const = 2.718281828459045f;
    const float scale = (2.0f + 2.0f * e_const) / (e_const - 1.0f);

    // Gather coordinates (threads 0..415)
    const bool gact = (tid < IK);
    const int  gi   = tid / K_DIM;
    const int  gk   = tid - gi * K_DIM;

    const int bid = blockIdx.x;
    const int cnt = (N_DIM - bid + GRID - 1) / GRID;   // 26 or 27

    // ---- Prologue: fill the first min(DEPTH,cnt) stages
    const int pro = (DEPTH < cnt) ? DEPTH : cnt;
    for (int it = 0; it < pro; ++it) {
        const int n = bid + it * GRID;
        const uint32_t bar = bar_base + it * 8;
        if (gact) {
            const int s = shifts[n * K_DIM + gk];
            gsh[it * IK + tid] = x[gi * N_DIM + s];
            mbar_arrive(bar);
        }
        if (tid == 0) {
            mbar_expect_tx(bar, ROW_BYTES);
            bulk_copy_g2s(smem_base + (uint32_t)(it * ROW_BYTES),
                          mask + (size_t)n * ROW_FLOATS, ROW_BYTES, bar);
        }
    }

    // ---- Main pipelined loop
    for (int it = 0; it < cnt; ++it) {
        const int s = it & (DEPTH - 1);
        const uint32_t ph = (it >> 2) & 1;
        const uint32_t bar = bar_base + s * 8;
        const int n = bid + it * GRID;

        // Prefetch gather for iteration it+DEPTH into a register
        const int  itf = it + DEPTH;
        const bool pf  = gact && (itf < cnt);
        float gv = 0.0f;
        if (pf) {
            const int nf = bid + itf * GRID;
            gv = x[gi * N_DIM + shifts[nf * K_DIM + gk]];
        }

        mbar_wait(bar, ph);

        // Consume: per-warp dot from shared (conflict-free LDS.128)
        const float4* m4 = (const float4*)(msh + s * ROW_FLOATS + warp * IK);
        const float4* g4 = (const float4*)(gsh + s * IK);

        float acc = 0.0f;
        #pragma unroll
        for (int j = 0; j < 3; ++j) {
            const int c = j * 32 + lane;
            const float4 m = m4[c];
            const float4 g = g4[c];
            const float4 w = wf[j];
            acc += m.x*w.x*g.x + m.y*w.y*g.y + m.z*w.z*g.z + m.w*w.w*g.w;
        }
        if (lane < 8) {
            const int c = 96 + lane;
            const float4 m = m4[c];
            const float4 g = g4[c];
            const float4 w = wf[3];
            acc += m.x*w.x*g.x + m.y*w.y*g.y + m.z*w.z*g.z + m.w*w.w*g.w;
        }

        #pragma unroll
        for (int off = 16; off > 0; off >>= 1)
            acc += __shfl_xor_sync(0xffffffffu, acc, off);

        if (lane == 0) {
            const float y = acc + bias;
            out[warp * N_DIM + n] = (1.0f / (1.0f + __expf(-y)) - 0.5f) * scale;
        }

        __syncthreads();   // everyone done reading stage s before refill

        // Refill stage s for iteration it+DEPTH
        if (itf < cnt) {
            if (gact) {
                gsh[s * IK + tid] = gv;
                mbar_arrive(bar);
            }
            if (tid == 0) {
                const int nf = bid + itf * GRID;
                mbar_expect_tx(bar, ROW_BYTES);
                bulk_copy_g2s(smem_base + (uint32_t)(s * ROW_BYTES),
                              mask + (size_t)nf * ROW_FLOATS, ROW_BYTES, bar);
            }
        }
    }
}

extern "C" void kernel_launch(void* const* d_in, const int* in_sizes, int n_in,
                              void* d_out, int out_size) {
    const float* x      = (const float*)d_in[0];
    const float* Wconv  = (const float*)d_in[1];
    const float* bconv  = (const float*)d_in[2];
    const float* mask   = (const float*)d_in[3];
    const int*   shifts = (const int*)d_in[4];
    float* out          = (float*)d_out;

    cudaFuncSetAttribute(plaq_kernel,
                         cudaFuncAttributeMaxDynamicSharedMemorySize, SMEM_TOTAL);
    plaq_kernel<<<GRID, THREADS, SMEM_TOTAL>>>(x, Wconv, bconv, mask, shifts, out);
}